// round 2
// baseline (speedup 1.0000x reference)
#include <cuda_runtime.h>
#include <cstdint>
#include <math_constants.h>

// Problem constants (shape-specialized to this instance)
#define LQ   256
#define HKV  2
#define HQN  32
#define GPH  16      // query heads per kv head
#define DIM  128
#define SSEL 16      // selected blocks per (l, h)
#define BS   64      // keys per block

#define NTHREADS 128
#define SMEM_BYTES (64*128*4*2 + 16*128*4)   // K + V + Q = 73728

__device__ __forceinline__ void cp16(void* smem_dst, const void* gmem_src) {
    uint32_t a = (uint32_t)__cvta_generic_to_shared(smem_dst);
    asm volatile("cp.async.cg.shared.global [%0], [%1], 16;" :: "r"(a), "l"(gmem_src));
}

__global__ __launch_bounds__(NTHREADS, 3)
void hsa_prefill_kernel(const float* __restrict__ q,
                        const float* __restrict__ k,
                        const float* __restrict__ v,
                        const float* __restrict__ w,
                        const int*   __restrict__ bidx,
                        float* __restrict__ out)
{
    extern __shared__ float4 sm4[];
    float4* K4 = sm4;          // 64 rows x 32 chunks (float4) = 2048
    float4* V4 = sm4 + 2048;   // 2048
    float4* Q4 = sm4 + 4096;   // 16 rows x 32 chunks = 512

    const int t  = threadIdx.x;
    const int l  = (int)blockIdx.x >> 1;
    const int h  = (int)blockIdx.x & 1;
    const int i  = t & 15;          // lane-in-group (u dimension)
    const int gp = t >> 4;          // 0..7
    const int g0 = 2*gp, g1 = 2*gp + 1;

    // ---- load Q tile: 16 contiguous head rows (hq = h*16 .. h*16+15) ----
    const float4* qg = (const float4*)(q + ((size_t)l*HQN + h*GPH) * DIM);
    #pragma unroll
    for (int ci = t; ci < 512; ci += NTHREADS) Q4[ci] = qg[ci];

    const float sm_scale = 0.08838834764831844f; // 1/sqrt(128)

    float4 a00 = {0,0,0,0}, a01 = {0,0,0,0};  // o[g0][4i..], o[g0][64+4i..]
    float4 a10 = {0,0,0,0}, a11 = {0,0,0,0};  // o[g1]

    const int*   bi  = bidx + ((size_t)l*HKV + h) * SSEL;
    const float* w0p = w + ((size_t)l*HQN + h*GPH + g0) * SSEL;
    const float* w1p = w + ((size_t)l*HQN + h*GPH + g1) * SSEL;

    for (int s = 0; s < SSEL; ++s) {
        const int idx = __ldg(bi + s);          // uniform across CTA
        if (idx < 0) continue;

        // ---- async load K,V block (64 x 128 f32 each) into smem ----
        const float* kb = k + ((size_t)idx*BS*HKV + h) * DIM;
        const float* vb = v + ((size_t)idx*BS*HKV + h) * DIM;
        #pragma unroll
        for (int r = 0; r < 16; ++r) {
            int ci = t + (r << 7);              // 0..2047
            int u  = ci >> 5, c = ci & 31;
            const float* ks = kb + (size_t)u*(HKV*DIM) + c*4;
            const float* vs = vb + (size_t)u*(HKV*DIM) + c*4;
            cp16(&K4[ci], ks);
            cp16(&V4[ci], vs);
        }
        asm volatile("cp.async.commit_group;");
        asm volatile("cp.async.wait_group 0;");
        __syncthreads();

        // ---- QK^T: thread computes scores for g0,g1 x u = 4i+j ----
        float s0[4] = {0,0,0,0}, s1[4] = {0,0,0,0};
        #pragma unroll 4
        for (int c = 0; c < 32; ++c) {
            const int cc = (c + i) & 31;        // rotate to avoid bank conflicts
            const float4 qa = Q4[g0*32 + cc];
            const float4 qb = Q4[g1*32 + cc];
            #pragma unroll
            for (int j = 0; j < 4; ++j) {
                const float4 kv = K4[((i << 2) + j)*32 + cc];
                s0[j] += qa.x*kv.x + qa.y*kv.y + qa.z*kv.z + qa.w*kv.w;
                s1[j] += qb.x*kv.x + qb.y*kv.y + qb.z*kv.z + qb.w*kv.w;
            }
        }

        // ---- per-block softmax over the 64 keys (width-16 shuffle groups) ----
        float m0 = -CUDART_INF_F, m1 = -CUDART_INF_F;
        #pragma unroll
        for (int j = 0; j < 4; ++j) {
            s0[j] *= sm_scale; s1[j] *= sm_scale;
            m0 = fmaxf(m0, s0[j]); m1 = fmaxf(m1, s1[j]);
        }
        #pragma unroll
        for (int o = 8; o; o >>= 1) {
            m0 = fmaxf(m0, __shfl_xor_sync(0xffffffffu, m0, o, 16));
            m1 = fmaxf(m1, __shfl_xor_sync(0xffffffffu, m1, o, 16));
        }
        float e0[4], e1[4];
        float sum0 = 0.f, sum1 = 0.f;
        #pragma unroll
        for (int j = 0; j < 4; ++j) {
            e0[j] = __expf(s0[j] - m0); sum0 += e0[j];
            e1[j] = __expf(s1[j] - m1); sum1 += e1[j];
        }
        #pragma unroll
        for (int o = 8; o; o >>= 1) {
            sum0 += __shfl_xor_sync(0xffffffffu, sum0, o, 16);
            sum1 += __shfl_xor_sync(0xffffffffu, sum1, o, 16);
        }
        const float c0 = __ldg(w0p + s) / sum0;
        const float c1 = __ldg(w1p + s) / sum1;
        #pragma unroll
        for (int j = 0; j < 4; ++j) { e0[j] *= c0; e1[j] *= c1; }

        // ---- P @ V: broadcast p via shuffle, accumulate o in registers ----
        #pragma unroll
        for (int j = 0; j < 4; ++j) {
            #pragma unroll
            for (int src = 0; src < 16; ++src) {
                const float p0 = __shfl_sync(0xffffffffu, e0[j], src, 16);
                const float p1 = __shfl_sync(0xffffffffu, e1[j], src, 16);
                const int u = (src << 2) + j;
                const float4 va = V4[u*32 + i];
                const float4 vb2 = V4[u*32 + i + 16];
                a00.x += p0*va.x;  a00.y += p0*va.y;  a00.z += p0*va.z;  a00.w += p0*va.w;
                a01.x += p0*vb2.x; a01.y += p0*vb2.y; a01.z += p0*vb2.z; a01.w += p0*vb2.w;
                a10.x += p1*va.x;  a10.y += p1*va.y;  a10.z += p1*va.z;  a10.w += p1*va.w;
                a11.x += p1*vb2.x; a11.y += p1*vb2.y; a11.z += p1*vb2.z; a11.w += p1*vb2.w;
            }
        }
        __syncthreads();  // protect K4/V4 before next block's load
    }

    // ---- write output: o[l, h*16+g, :] ----
    float4* o0 = (float4*)(out + ((size_t)l*HQN + h*GPH + g0) * DIM);
    float4* o1 = (float4*)(out + ((size_t)l*HQN + h*GPH + g1) * DIM);
    o0[i]      = a00;
    o0[i + 16] = a01;
    o1[i]      = a10;
    o1[i + 16] = a11;
}

extern "C" void kernel_launch(void* const* d_in, const int* in_sizes, int n_in,
                              void* d_out, int out_size)
{
    (void)in_sizes; (void)n_in; (void)out_size;
    const float* q    = (const float*)d_in[0];
    const float* k    = (const float*)d_in[1];
    const float* v    = (const float*)d_in[2];
    const float* w    = (const float*)d_in[3];
    const int*   bidx = (const int*)d_in[4];
    float* out = (float*)d_out;

    static bool attr_set = false;
    if (!attr_set) {
        cudaFuncSetAttribute(hsa_prefill_kernel,
                             cudaFuncAttributeMaxDynamicSharedMemorySize, SMEM_BYTES);
        attr_set = true;
    }

    dim3 grid(LQ * HKV);   // 512 CTAs: (l, h)
    dim3 block(NTHREADS);
    hsa_prefill_kernel<<<grid, block, SMEM_BYTES>>>(q, k, v, w, bidx, out);
}

// round 5
// speedup vs baseline: 1.2606x; 1.2606x over previous
#include <cuda_runtime.h>
#include <cstdint>
#include <math_constants.h>

// Shape-specialized constants
#define LQ   256
#define HKV  2
#define HQN  32
#define GPH  16
#define DIM  128
#define SSEL 16
#define BS   64

#define NTHREADS 128
// K(64x32 float4) + V(64x32) + Q(16x32) = 4608 float4 = 73728 B
#define SMEM_BYTES (4608 * 16)

__device__ __forceinline__ void cp16(void* smem_dst, const void* gmem_src) {
    uint32_t a = (uint32_t)__cvta_generic_to_shared(smem_dst);
    asm volatile("cp.async.cg.shared.global [%0], [%1], 16;" :: "r"(a), "l"(gmem_src));
}
// packed f32x2 fma: d.lo += a.lo*b.lo; d.hi += a.hi*b.hi
__device__ __forceinline__ void ffma2(unsigned long long& d, unsigned long long a,
                                      unsigned long long b) {
    asm("fma.rn.f32x2 %0, %1, %2, %0;" : "+l"(d) : "l"(a), "l"(b));
}
__device__ __forceinline__ unsigned long long splat2(float x) {
    unsigned long long r;
    asm("mov.b64 %0, {%1, %1};" : "=l"(r) : "f"(x));
    return r;
}
__device__ __forceinline__ float hadd2(unsigned long long v) {
    float lo, hi;
    asm("mov.b64 {%0, %1}, %2;" : "=f"(lo), "=f"(hi) : "l"(v));
    return lo + hi;
}
__device__ __forceinline__ float2 unpack2(unsigned long long v) {
    float2 f;
    asm("mov.b64 {%0, %1}, %2;" : "=f"(f.x), "=f"(f.y) : "l"(v));
    return f;
}

__global__ __launch_bounds__(NTHREADS, 3)
void hsa_prefill_kernel(const float* __restrict__ q,
                        const float* __restrict__ k,
                        const float* __restrict__ v,
                        const float* __restrict__ w,
                        const int*   __restrict__ bidx,
                        float* __restrict__ out)
{
    extern __shared__ float4 sm4[];
    float4* K4 = sm4;          // 64 rows x 32 chunks, XOR-swizzled
    float4* V4 = sm4 + 2048;   // same layout
    float4* Q4 = sm4 + 4096;   // 16 rows x 32 chunks, linear

    const int t    = threadIdx.x;
    const int lane = t & 31;
    const int wid  = t >> 5;           // warp owns heads g = 4*wid .. 4*wid+3
    const int l    = (int)blockIdx.x >> 1;
    const int h    = (int)blockIdx.x & 1;
    const int sw   = lane & 7;         // row swizzle key for u=lane (and lane+32)

    // ---- Q tile: 16 head rows for this (l, h) ----
    const float4* qg = (const float4*)(q + ((size_t)l*HQN + h*GPH) * DIM);
    #pragma unroll
    for (int ci = t; ci < 512; ci += NTHREADS) Q4[ci] = qg[ci];

    const float sm_scale = 0.08838834764831844f;  // 1/sqrt(128)

    unsigned long long oAcc[4][2] = {};  // o[g][chunk lane], 2 f32x2 pairs each

    const int*   bi = bidx + ((size_t)l*HKV + h) * SSEL;
    const float* wp = w + ((size_t)l*HQN + h*GPH + 4*wid) * SSEL;

    #pragma unroll 1
    for (int s = 0; s < SSEL; ++s) {
        const int idx = __ldg(bi + s);          // uniform across CTA
        if (idx >= 0) {
            // ---- async load K,V block (64 x 128 f32 each), swizzled ----
            const float* kb = k + ((size_t)idx*BS*HKV + h) * DIM;
            const float* vb = v + ((size_t)idx*BS*HKV + h) * DIM;
            #pragma unroll
            for (int r = 0; r < 16; ++r) {
                int ci = t + (r << 7);
                int u = ci >> 5, c = ci & 31;
                int dci = (u << 5) | (c ^ (u & 7));
                cp16(&K4[dci], kb + (size_t)u*(HKV*DIM) + c*4);
                cp16(&V4[dci], vb + (size_t)u*(HKV*DIM) + c*4);
            }
            asm volatile("cp.async.commit_group;");
            asm volatile("cp.async.wait_group 0;");
            __syncthreads();

            // ---- QK^T: lane computes s[g][u=lane], s[g][u=lane+32], g=4w..4w+3
            unsigned long long sAcc[4][2] = {};
            const float4* Krow0 = K4 + (lane << 5);
            const float4* Krow1 = K4 + ((lane + 32) << 5);
            const float4* Qb    = Q4 + (wid << 7);
            #pragma unroll 8
            for (int c = 0; c < 32; ++c) {
                const int cs = c ^ sw;
                const ulonglong2 k0 = *(const ulonglong2*)&Krow0[cs];
                const ulonglong2 k1 = *(const ulonglong2*)&Krow1[cs];
                #pragma unroll
                for (int g = 0; g < 4; ++g) {
                    const ulonglong2 qq = *(const ulonglong2*)&Qb[(g << 5) + c]; // broadcast
                    ffma2(sAcc[g][0], qq.x, k0.x);
                    ffma2(sAcc[g][0], qq.y, k0.y);
                    ffma2(sAcc[g][1], qq.x, k1.x);
                    ffma2(sAcc[g][1], qq.y, k1.y);
                }
            }

            // ---- per-block softmax over 64 keys (full-warp reductions) ----
            float ev[4][2];
            #pragma unroll
            for (int g = 0; g < 4; ++g) {
                float s0 = hadd2(sAcc[g][0]) * sm_scale;
                float s1 = hadd2(sAcc[g][1]) * sm_scale;
                float m = fmaxf(s0, s1);
                #pragma unroll
                for (int o = 16; o; o >>= 1)
                    m = fmaxf(m, __shfl_xor_sync(0xffffffffu, m, o));
                float e0 = __expf(s0 - m), e1 = __expf(s1 - m);
                float sum = e0 + e1;
                #pragma unroll
                for (int o = 16; o; o >>= 1)
                    sum += __shfl_xor_sync(0xffffffffu, sum, o);
                const float coef = __ldg(wp + g*SSEL + s) / sum;
                ev[g][0] = e0 * coef;
                ev[g][1] = e1 * coef;
            }

            // all warps are done reading K — safe to overlay P on the K region
            __syncthreads();
            float4* Pw = K4 + (wid << 6);   // per-warp 64-entry P[u] = {p(g0..g3)}
            Pw[lane]      = make_float4(ev[0][0], ev[1][0], ev[2][0], ev[3][0]);
            Pw[lane + 32] = make_float4(ev[0][1], ev[1][1], ev[2][1], ev[3][1]);
            __syncwarp();

            // ---- P @ V: lane owns D-chunk `lane` (4 floats) for 4 heads ----
            #pragma unroll 8
            for (int u = 0; u < 64; ++u) {
                const float4 p4 = Pw[u];                                  // broadcast
                const ulonglong2 vv =
                    *(const ulonglong2*)&V4[(u << 5) | (lane ^ (u & 7))]; // conflict-free
                unsigned long long p;
                p = splat2(p4.x); ffma2(oAcc[0][0], vv.x, p); ffma2(oAcc[0][1], vv.y, p);
                p = splat2(p4.y); ffma2(oAcc[1][0], vv.x, p); ffma2(oAcc[1][1], vv.y, p);
                p = splat2(p4.z); ffma2(oAcc[2][0], vv.x, p); ffma2(oAcc[2][1], vv.y, p);
                p = splat2(p4.w); ffma2(oAcc[3][0], vv.x, p); ffma2(oAcc[3][1], vv.y, p);
            }
        }
        __syncthreads();  // protect K4/V4 (and P overlay) before next block's load
    }

    // ---- write output: o[l, h*16 + 4*wid + g, 4*lane .. 4*lane+3] ----
    #pragma unroll
    for (int g = 0; g < 4; ++g) {
        const float2 lo = unpack2(oAcc[g][0]);
        const float2 hi = unpack2(oAcc[g][1]);
        float4* op = (float4*)(out + ((size_t)l*HQN + h*GPH + 4*wid + g) * DIM);
        op[lane] = make_float4(lo.x, lo.y, hi.x, hi.y);
    }
}

extern "C" void kernel_launch(void* const* d_in, const int* in_sizes, int n_in,
                              void* d_out, int out_size)
{
    (void)in_sizes; (void)n_in; (void)out_size;
    const float* q    = (const float*)d_in[0];
    const float* k    = (const float*)d_in[1];
    const float* v    = (const float*)d_in[2];
    const float* w    = (const float*)d_in[3];
    const int*   bidx = (const int*)d_in[4];
    float* out = (float*)d_out;

    static bool attr_set = false;
    if (!attr_set) {
        cudaFuncSetAttribute(hsa_prefill_kernel,
                             cudaFuncAttributeMaxDynamicSharedMemorySize, SMEM_BYTES);
        attr_set = true;
    }

    dim3 grid(LQ * HKV);
    dim3 block(NTHREADS);
    hsa_prefill_kernel<<<grid, block, SMEM_BYTES>>>(q, k, v, w, bidx, out);
}